// round 5
// baseline (speedup 1.0000x reference)
#include <cuda_runtime.h>

// FM second-order interaction:
//   out[b] = 0.5 * ( sum_k (x@v)[b,k]^2  -  sum_f x[b,f]^2 * w[f] ),
//   w[f] = sum_k v[f,k]^2
// B=16384, F=2048, K=64, all fp32.

#define B_ROWS 16384
#define F_DIM  2048
#define K_DIM  64

#define MT      64      // rows per block tile
#define FC      64      // f-chunk
#define MTP     68      // padded row length for transposed x tile (mult of 4, conflict-light)
#define VP      68      // padded row length for v tile
#define THREADS 128

__device__ float g_w[F_DIM];

// ---------------------------------------------------------------------------
// Precompute w[f] = sum_k v[f,k]^2   (2048 rows of 64 floats; trivial)
// ---------------------------------------------------------------------------
__global__ void fm_prep_w(const float* __restrict__ v) {
    int f = blockIdx.x * blockDim.x + threadIdx.x;
    if (f < F_DIM) {
        const float4* row = reinterpret_cast<const float4*>(v + (size_t)f * K_DIM);
        float s = 0.f;
#pragma unroll
        for (int i = 0; i < K_DIM / 4; i++) {
            float4 a = row[i];
            s += a.x * a.x + a.y * a.y + a.z * a.z + a.w * a.w;
        }
        g_w[f] = s;
    }
}

// ---------------------------------------------------------------------------
// Main kernel: one block = 64 rows x 64 k-cols, looped over F in chunks of 64.
// Thread (rg,cg): rg = tid/8 in [0,16), cg = tid%8 in [0,8).
// Owns rows r0..r0+3 (r0 = 4*rg) and cols c0..c0+7 (c0 = 8*cg).
// Accumulators are packed f32x2 pairs along the column axis -> fma.rn.f32x2.
// ---------------------------------------------------------------------------
__global__ __launch_bounds__(THREADS)
void fm_main(const float* __restrict__ x,
             const float* __restrict__ v,
             float* __restrict__ out) {
    __shared__ float xs[FC][MTP];      // transposed x chunk: xs[f_local][row_local]
    __shared__ float vs[FC][VP];       // v chunk:            vs[f_local][k]
    __shared__ float dred[THREADS];    // per-thread diag partials

    const int tid     = threadIdx.x;
    const int rowBase = blockIdx.x * MT;

    // staging mapping: thread covers one fixed local row (lrow), half the f-chunk
    const int lrow = tid >> 1;          // 0..63
    const int ofs  = (tid & 1) * 32;    // 0 or 32 (floats within the 64-wide chunk)

    // compute mapping
    const int rg = tid >> 3;            // 0..15
    const int cg = tid & 7;             // 0..7
    const int r0 = rg * 4;
    const int c0 = cg * 8;

    unsigned long long acc[4][4];       // [row][col-pair], each = packed (f32,f32)
#pragma unroll
    for (int i = 0; i < 4; i++)
#pragma unroll
        for (int p = 0; p < 4; p++) acc[i][p] = 0ull;

    float dloc = 0.f;                   // sum_f x[lrow,f]^2 * w[f] over this thread's coverage

    for (int f0 = 0; f0 < F_DIM; f0 += FC) {
        __syncthreads();   // previous compute done reading smem

        // ---- stage x chunk (transposed) + fold diag term into the load ----
        {
            const float* xrow = x + (size_t)(rowBase + lrow) * F_DIM + f0 + ofs;
            const float* wrow = g_w + f0 + ofs;
#pragma unroll
            for (int it = 0; it < 8; it++) {
                float4 a  = *reinterpret_cast<const float4*>(xrow + 4 * it);
                float4 w4 = *reinterpret_cast<const float4*>(wrow + 4 * it);
                dloc += a.x * a.x * w4.x + a.y * a.y * w4.y
                      + a.z * a.z * w4.z + a.w * a.w * w4.w;
                int fl = ofs + 4 * it;
                xs[fl + 0][lrow] = a.x;
                xs[fl + 1][lrow] = a.y;
                xs[fl + 2][lrow] = a.z;
                xs[fl + 3][lrow] = a.w;
            }
        }

        // ---- stage v chunk ----
        {
            const float* vrow = v + (size_t)(f0 + lrow) * K_DIM + ofs;
#pragma unroll
            for (int it = 0; it < 8; it++) {
                float4 a = *reinterpret_cast<const float4*>(vrow + 4 * it);
                *reinterpret_cast<float4*>(&vs[lrow][ofs + 4 * it]) = a;
            }
        }
        __syncthreads();

        // ---- compute: 64 outer-product rank-1 updates ----
#pragma unroll 4
        for (int fl = 0; fl < FC; fl++) {
            float4 xv = *reinterpret_cast<const float4*>(&xs[fl][r0]);
            longlong2 va = *reinterpret_cast<const longlong2*>(&vs[fl][c0]);
            longlong2 vb = *reinterpret_cast<const longlong2*>(&vs[fl][c0 + 4]);
            unsigned long long v0 = (unsigned long long)va.x;
            unsigned long long v1 = (unsigned long long)va.y;
            unsigned long long v2 = (unsigned long long)vb.x;
            unsigned long long v3 = (unsigned long long)vb.y;

            unsigned long long xp0, xp1, xp2, xp3;
            asm("mov.b64 %0, {%1, %1};" : "=l"(xp0) : "r"(__float_as_uint(xv.x)));
            asm("mov.b64 %0, {%1, %1};" : "=l"(xp1) : "r"(__float_as_uint(xv.y)));
            asm("mov.b64 %0, {%1, %1};" : "=l"(xp2) : "r"(__float_as_uint(xv.z)));
            asm("mov.b64 %0, {%1, %1};" : "=l"(xp3) : "r"(__float_as_uint(xv.w)));

#define FMA2(ACC, XP, VV) \
            asm("fma.rn.f32x2 %0, %1, %2, %0;" : "+l"(ACC) : "l"(XP), "l"(VV))

            FMA2(acc[0][0], xp0, v0); FMA2(acc[0][1], xp0, v1);
            FMA2(acc[0][2], xp0, v2); FMA2(acc[0][3], xp0, v3);
            FMA2(acc[1][0], xp1, v0); FMA2(acc[1][1], xp1, v1);
            FMA2(acc[1][2], xp1, v2); FMA2(acc[1][3], xp1, v3);
            FMA2(acc[2][0], xp2, v0); FMA2(acc[2][1], xp2, v1);
            FMA2(acc[2][2], xp2, v2); FMA2(acc[2][3], xp2, v3);
            FMA2(acc[3][0], xp3, v0); FMA2(acc[3][1], xp3, v1);
            FMA2(acc[3][2], xp3, v2); FMA2(acc[3][3], xp3, v3);
#undef FMA2
        }
    }

    // ---- diag partials to smem ----
    dred[tid] = dloc;
    __syncthreads();

    // ---- epilogue: per-row sum of squares over k, reduce across 8 col-lanes ----
#pragma unroll
    for (int i = 0; i < 4; i++) {
        float s = 0.f;
#pragma unroll
        for (int p = 0; p < 4; p++) {
            float lo = __uint_as_float((unsigned)(acc[i][p] & 0xffffffffull));
            float hi = __uint_as_float((unsigned)(acc[i][p] >> 32));
            s += lo * lo + hi * hi;
        }
        // 8 lanes (cg 0..7) of the same row-group are consecutive in the warp
        s += __shfl_xor_sync(0xffffffffu, s, 1);
        s += __shfl_xor_sync(0xffffffffu, s, 2);
        s += __shfl_xor_sync(0xffffffffu, s, 4);
        if (cg == 0) {
            int r = r0 + i;                          // local row 0..63
            float d = dred[2 * r] + dred[2 * r + 1]; // the two staging threads of row r
            out[rowBase + r] = 0.5f * (s - d);
        }
    }
}

// ---------------------------------------------------------------------------
extern "C" void kernel_launch(void* const* d_in, const int* in_sizes, int n_in,
                              void* d_out, int out_size) {
    const float* x = (const float*)d_in[0];   // (16384, 2048) fp32
    const float* v = (const float*)d_in[1];   // (2048, 64)    fp32
    float* out = (float*)d_out;               // (16384, 1)    fp32

    fm_prep_w<<<F_DIM / 128, 128>>>(v);
    fm_main<<<B_ROWS / MT, THREADS>>>(x, v, out);
}